// round 1
// baseline (speedup 1.0000x reference)
#include <cuda_runtime.h>

// GraphPooling: B=16, N=4096, F=8, H=64, C=256 (shapes fixed by setup_inputs)
// out[b,c,f,h] = sum_{n: seg[n]==c} softmax_weight(b,n) * x[b,n,f,h]
// weight from per-(b,segment) softmax of scores[b,n] = dot(x[b,n,:,:], W)/F + bias.

#define BB   16
#define NN   4096
#define FF   8
#define HH   64
#define CC   256
#define ROW  512            // F*H floats per (b,n) row
#define MAXPER 96           // max nodes per segment (Binomial(4096,1/256); P(>96) ~ 0)

__device__ int g_list[CC * MAXPER];
__device__ int g_cnt[CC];

// One warp per segment: ordered (increasing n) compaction -> deterministic order.
__global__ void build_lists_kernel(const int* __restrict__ seg) {
    const int c    = blockIdx.x;
    const int lane = threadIdx.x;
    int base = 0;
    for (int n0 = 0; n0 < NN; n0 += 32) {
        const int n = n0 + lane;
        const int s = seg[n];
        const unsigned mask = __ballot_sync(0xFFFFFFFFu, s == c);
        if (s == c) {
            const int pos = base + __popc(mask & ((1u << lane) - 1u));
            if (pos < MAXPER) g_list[c * MAXPER + pos] = n;
        }
        base += __popc(mask);
    }
    if (lane == 0) g_cnt[c] = base < MAXPER ? base : MAXPER;
}

// One block per (c, b). 128 threads.
// Phase 1: warp-per-node score (reads the rows -> warms L1/L2).
// Phase 2: warp-0 softmax over <=96 scores.
// Phase 3: 128-thread float4 weighted accumulate (re-reads hit cache), one store.
__global__ __launch_bounds__(128) void pool_kernel(
    const float* __restrict__ x,
    const float* __restrict__ W,
    const float* __restrict__ bias,
    float* __restrict__ out)
{
    __shared__ float s_score[MAXPER];
    __shared__ float s_w[MAXPER];
    __shared__ int   s_list[MAXPER];

    const int c    = blockIdx.x;
    const int b    = blockIdx.y;
    const int tid  = threadIdx.x;
    const int wid  = tid >> 5;
    const int lane = tid & 31;

    const int cnt = g_cnt[c];
    if (tid < cnt) s_list[tid] = g_list[c * MAXPER + tid];
    __syncthreads();

    // ---- Phase 1: scores (warp i handles nodes i, i+4, ...) ----
    // Row element index for (j, lane) is j*128 + lane*4; h = (lane*4) & 63.
    const float4 w4 = *(const float4*)(W + ((lane * 4) & 63));
    const float  bv = __ldg(bias);

    for (int i = wid; i < cnt; i += 4) {
        const float4* row = (const float4*)(x + (size_t)(b * NN + s_list[i]) * ROW);
        float acc = 0.f;
        #pragma unroll
        for (int j = 0; j < 4; ++j) {
            const float4 v = __ldg(row + j * 32 + lane);
            acc += v.x * w4.x + v.y * w4.y + v.z * w4.z + v.w * w4.w;
        }
        #pragma unroll
        for (int off = 16; off; off >>= 1)
            acc += __shfl_xor_sync(0xFFFFFFFFu, acc, off);
        if (lane == 0) s_score[i] = acc * 0.125f + bv;   // /F + bias
    }
    __syncthreads();

    // ---- Phase 2: softmax weights (warp 0) ----
    if (wid == 0 && cnt > 0) {
        float m = -3.402823466e+38f;
        for (int i = lane; i < cnt; i += 32) m = fmaxf(m, s_score[i]);
        #pragma unroll
        for (int off = 16; off; off >>= 1)
            m = fmaxf(m, __shfl_xor_sync(0xFFFFFFFFu, m, off));

        float d = 0.f;
        for (int i = lane; i < cnt; i += 32) {
            const float e = __expf(s_score[i] - m);
            s_w[i] = e;
            d += e;
        }
        #pragma unroll
        for (int off = 16; off; off >>= 1)
            d += __shfl_xor_sync(0xFFFFFFFFu, d, off);

        const float inv = 1.f / d;
        for (int i = lane; i < cnt; i += 32) s_w[i] *= inv;
    }
    __syncthreads();

    // ---- Phase 3: weighted accumulate, sequential over list -> deterministic ----
    float4 acc = make_float4(0.f, 0.f, 0.f, 0.f);
    for (int i = 0; i < cnt; ++i) {
        const float  ww  = s_w[i];
        const float4* row = (const float4*)(x + (size_t)(b * NN + s_list[i]) * ROW);
        const float4 v = __ldg(row + tid);
        acc.x = fmaf(ww, v.x, acc.x);
        acc.y = fmaf(ww, v.y, acc.y);
        acc.z = fmaf(ww, v.z, acc.z);
        acc.w = fmaf(ww, v.w, acc.w);
    }
    ((float4*)out)[(size_t)(b * CC + c) * (ROW / 4) + tid] = acc;
}

extern "C" void kernel_launch(void* const* d_in, const int* in_sizes, int n_in,
                              void* d_out, int out_size) {
    const float* x    = (const float*)d_in[0];   // [B,N,F,H] f32
    const float* W    = (const float*)d_in[1];   // [H,1]     f32
    const float* bias = (const float*)d_in[2];   // [1]       f32
    const int*   seg  = (const int*)d_in[3];     // [N]       int32

    build_lists_kernel<<<CC, 32>>>(seg);
    pool_kernel<<<dim3(CC, BB), 128>>>(x, W, bias, (float*)d_out);
}

// round 2
// speedup vs baseline: 1.0008x; 1.0008x over previous
#include <cuda_runtime.h>

// GraphPooling: B=16, N=4096, F=8, H=64, C=256
// out[b,c,f,h] = sum_{n: seg[n]==c} softmax_w(b,n) * x[b,n,f,h]
// score[b,n] = dot(x[b,n,:,:], W_rep)/F + bias ; softmax per (b, segment).

#define BB   16
#define NN   4096
#define FF   8
#define HH   64
#define CC   256
#define ROW  512
#define MAXPER 96
#define LW   16          // list-builder warps (512 threads)

__device__ int g_list[CC * MAXPER];
__device__ int g_cnt[CC];

// One block, 512 threads. Stage seg in smem, per-warp-chunk histogram,
// exclusive scan across chunks, ordered placement via match_any ranks.
// Global order = increasing node index (deterministic).
__global__ __launch_bounds__(512) void build_lists_kernel(const int* __restrict__ seg) {
    __shared__ int s_seg[NN];          // 16 KB
    __shared__ int s_hist[LW][CC];     // 16 KB

    const int tid  = threadIdx.x;
    const int w    = tid >> 5;
    const int lane = tid & 31;

    for (int i = tid; i < NN; i += 512)      s_seg[i] = seg[i];
    for (int i = tid; i < LW * CC; i += 512) ((int*)s_hist)[i] = 0;
    __syncthreads();

    const int base_n = w * (NN / LW);        // 256-node chunk per warp
    #pragma unroll
    for (int r = 0; r < (NN / LW) / 32; ++r) // 8 rounds
        atomicAdd(&s_hist[w][s_seg[base_n + r * 32 + lane]], 1);
    __syncthreads();

    if (tid < CC) {
        int sum = 0;
        #pragma unroll
        for (int ww = 0; ww < LW; ++ww) {
            const int t = s_hist[ww][tid];
            s_hist[ww][tid] = sum;           // exclusive offset for chunk ww
            sum += t;
        }
        g_cnt[tid] = sum < MAXPER ? sum : MAXPER;
    }
    __syncthreads();

    #pragma unroll
    for (int r = 0; r < (NN / LW) / 32; ++r) {
        const int n = base_n + r * 32 + lane;
        const int c = s_seg[n];
        const unsigned m = __match_any_sync(0xFFFFFFFFu, c);
        const int rank = __popc(m & ((1u << lane) - 1u));
        const int base = s_hist[w][c];       // same value for all lanes of group
        const int pos  = base + rank;
        if (pos < MAXPER) g_list[c * MAXPER + pos] = n;
        __syncwarp();
        if (rank == 0) s_hist[w][c] = base + __popc(m);  // one writer per group
        __syncwarp();
    }
}

// One block per (c, b), 128 threads.
__global__ __launch_bounds__(128) void pool_kernel(
    const float* __restrict__ x,
    const float* __restrict__ W,
    const float* __restrict__ bias,
    float* __restrict__ out)
{
    __shared__ float s_score[MAXPER];
    __shared__ float s_w[MAXPER];
    __shared__ int   s_list[MAXPER];

    const int c    = blockIdx.x;
    const int b    = blockIdx.y;
    const int tid  = threadIdx.x;
    const int wid  = tid >> 5;
    const int lane = tid & 31;

    const int cnt = g_cnt[c];
    if (tid < cnt) s_list[tid] = g_list[c * MAXPER + tid];
    __syncthreads();

    // ---- Phase 1: scores. Two rows per warp-iteration -> 8 outstanding loads.
    const float4 w4 = *(const float4*)(W + ((lane * 4) & 63));
    const float  bv = __ldg(bias);
    const float* xb = x + (size_t)b * NN * ROW;

    for (int i0 = wid; i0 < cnt; i0 += 8) {
        const int  i1   = i0 + 4;
        const bool has1 = i1 < cnt;
        const float4* r0 = (const float4*)(xb + (size_t)s_list[i0] * ROW);
        const float4* r1 = (const float4*)(xb + (size_t)s_list[has1 ? i1 : i0] * ROW);
        float4 v0[4], v1[4];
        #pragma unroll
        for (int j = 0; j < 4; ++j) v0[j] = __ldg(r0 + j * 32 + lane);
        #pragma unroll
        for (int j = 0; j < 4; ++j) v1[j] = __ldg(r1 + j * 32 + lane);

        float a0 = 0.f, a1 = 0.f;
        #pragma unroll
        for (int j = 0; j < 4; ++j) {
            a0 += v0[j].x * w4.x + v0[j].y * w4.y + v0[j].z * w4.z + v0[j].w * w4.w;
            a1 += v1[j].x * w4.x + v1[j].y * w4.y + v1[j].z * w4.z + v1[j].w * w4.w;
        }
        #pragma unroll
        for (int off = 16; off; off >>= 1) {
            a0 += __shfl_xor_sync(0xFFFFFFFFu, a0, off);
            a1 += __shfl_xor_sync(0xFFFFFFFFu, a1, off);
        }
        if (lane == 0) {
            s_score[i0] = a0 * 0.125f + bv;
            if (has1) s_score[i1] = a1 * 0.125f + bv;
        }
    }
    __syncthreads();

    // ---- Phase 2: softmax weights (warp 0).
    if (wid == 0 && cnt > 0) {
        float m = -3.402823466e+38f;
        for (int i = lane; i < cnt; i += 32) m = fmaxf(m, s_score[i]);
        #pragma unroll
        for (int off = 16; off; off >>= 1)
            m = fmaxf(m, __shfl_xor_sync(0xFFFFFFFFu, m, off));

        float d = 0.f;
        for (int i = lane; i < cnt; i += 32) {
            const float e = __expf(s_score[i] - m);
            s_w[i] = e;
            d += e;
        }
        #pragma unroll
        for (int off = 16; off; off >>= 1)
            d += __shfl_xor_sync(0xFFFFFFFFu, d, off);

        const float inv = 1.f / d;
        for (int i = lane; i < cnt; i += 32) s_w[i] *= inv;
    }
    __syncthreads();

    // ---- Phase 3: weighted accumulate, unroll x4 (loads batched, FMAs in i-order).
    float4 acc = make_float4(0.f, 0.f, 0.f, 0.f);
    int i = 0;
    for (; i + 4 <= cnt; i += 4) {
        const float4 v0 = __ldg((const float4*)(xb + (size_t)s_list[i]     * ROW) + tid);
        const float4 v1 = __ldg((const float4*)(xb + (size_t)s_list[i + 1] * ROW) + tid);
        const float4 v2 = __ldg((const float4*)(xb + (size_t)s_list[i + 2] * ROW) + tid);
        const float4 v3 = __ldg((const float4*)(xb + (size_t)s_list[i + 3] * ROW) + tid);
        const float w0 = s_w[i], w1 = s_w[i + 1], w2 = s_w[i + 2], w3 = s_w[i + 3];
        acc.x = fmaf(w0, v0.x, acc.x); acc.y = fmaf(w0, v0.y, acc.y);
        acc.z = fmaf(w0, v0.z, acc.z); acc.w = fmaf(w0, v0.w, acc.w);
        acc.x = fmaf(w1, v1.x, acc.x); acc.y = fmaf(w1, v1.y, acc.y);
        acc.z = fmaf(w1, v1.z, acc.z); acc.w = fmaf(w1, v1.w, acc.w);
        acc.x = fmaf(w2, v2.x, acc.x); acc.y = fmaf(w2, v2.y, acc.y);
        acc.z = fmaf(w2, v2.z, acc.z); acc.w = fmaf(w2, v2.w, acc.w);
        acc.x = fmaf(w3, v3.x, acc.x); acc.y = fmaf(w3, v3.y, acc.y);
        acc.z = fmaf(w3, v3.z, acc.z); acc.w = fmaf(w3, v3.w, acc.w);
    }
    for (; i < cnt; ++i) {
        const float4 v = __ldg((const float4*)(xb + (size_t)s_list[i] * ROW) + tid);
        const float ww = s_w[i];
        acc.x = fmaf(ww, v.x, acc.x); acc.y = fmaf(ww, v.y, acc.y);
        acc.z = fmaf(ww, v.z, acc.z); acc.w = fmaf(ww, v.w, acc.w);
    }
    ((float4*)out)[(size_t)(b * CC + c) * (ROW / 4) + tid] = acc;
}

extern "C" void kernel_launch(void* const* d_in, const int* in_sizes, int n_in,
                              void* d_out, int out_size) {
    const float* x    = (const float*)d_in[0];
    const float* W    = (const float*)d_in[1];
    const float* bias = (const float*)d_in[2];
    const int*   seg  = (const int*)d_in[3];

    build_lists_kernel<<<1, 512>>>(seg);
    pool_kernel<<<dim3(CC, BB), 128>>>(x, W, bias, (float*)d_out);
}

// round 4
// speedup vs baseline: 1.0109x; 1.0101x over previous
#include <cuda_runtime.h>
#include <float.h>

// GraphPooling: B=16, N=4096, F=8, H=64, C=256
// out[b,c,:,:] = sum_{n: seg[n]==c} softmax_w(b,n) * x[b,n,:,:]
// score[b,n] = (sum_e x[b,n,e] * W[h(e)]) / F + bias ; softmax per (b, segment).
// Single-pass: online softmax, each x row read from DRAM exactly once.

#define BB   16
#define NN   4096
#define FF   8
#define HH   64
#define CC   256
#define ROW  512
#define MAXPER 96

__device__ int g_list[CC * MAXPER];
__device__ int g_cnt[CC];

// Block c compacts segment c. Thread t owns contiguous chunk [t*32, t*32+32):
// concatenated order = increasing node index (deterministic).
__global__ __launch_bounds__(128) void build_lists_kernel(const int* __restrict__ seg) {
    __shared__ int s_seg[NN];        // 16 KB
    __shared__ int s_cnt[128];
    __shared__ int s_wtot[4];

    const int c    = blockIdx.x;
    const int tid  = threadIdx.x;
    const int lane = tid & 31;
    const int wid  = tid >> 5;

    for (int i = tid; i < NN / 4; i += 128)
        ((int4*)s_seg)[i] = ((const int4*)seg)[i];
    __syncthreads();

    // pass 1: count
    const int base = tid * 32;
    int cnt = 0;
    #pragma unroll
    for (int j = 0; j < 32; ++j) cnt += (s_seg[base + j] == c);

    // exclusive scan over 128 counts
    int incl = cnt;
    #pragma unroll
    for (int off = 1; off < 32; off <<= 1) {
        const int v = __shfl_up_sync(0xFFFFFFFFu, incl, off);
        if (lane >= off) incl += v;
    }
    if (lane == 31) s_wtot[wid] = incl;
    s_cnt[tid] = incl - cnt;
    __syncthreads();
    int wbase = 0;
    #pragma unroll
    for (int w = 0; w < 4; ++w) { if (w < wid) wbase += s_wtot[w]; }
    const int offset = s_cnt[tid] + wbase;

    if (tid == 127) {
        const int total = offset + cnt;
        g_cnt[c] = total < MAXPER ? total : MAXPER;
    }

    // pass 2: write
    int p = offset;
    #pragma unroll
    for (int j = 0; j < 32; ++j) {
        if (s_seg[base + j] == c) {
            if (p < MAXPER) g_list[c * MAXPER + p] = base + j;
            ++p;
        }
    }
}

// One block per (c, b), 128 threads. Thread tid owns the float4 at row offset tid*4.
__global__ __launch_bounds__(128) void pool_kernel(
    const float* __restrict__ x,
    const float* __restrict__ W,
    const float* __restrict__ bias,
    float* __restrict__ out)
{
    __shared__ int   s_list[MAXPER];
    __shared__ float s_red[2][4][4];   // [buf][warp][row-in-group]

    const int c    = blockIdx.x;
    const int b    = blockIdx.y;
    const int tid  = threadIdx.x;
    const int wid  = tid >> 5;
    const int lane = tid & 31;

    const int cnt = g_cnt[c];
    const size_t out_idx = (size_t)(b * CC + c) * (ROW / 4) + tid;
    if (cnt == 0) {
        ((float4*)out)[out_idx] = make_float4(0.f, 0.f, 0.f, 0.f);
        return;
    }
    if (tid < cnt) s_list[tid] = g_list[c * MAXPER + tid];
    __syncthreads();

    const float4 wv = *(const float4*)(W + ((tid * 4) & 63));
    const float  bv = __ldg(bias);
    const float* xb = x + (size_t)b * NN * ROW;

    const int G = (cnt + 3) >> 2;      // 4-row groups

    float m = -FLT_MAX, d = 0.f;
    float4 acc = make_float4(0.f, 0.f, 0.f, 0.f);

    // group 0 loads (padded rows alias the last valid row; masked via -FLT_MAX score)
    float4 cur[4];
    {
        int i0 = 0, i1 = 1 < cnt ? 1 : cnt - 1,
            i2 = 2 < cnt ? 2 : cnt - 1, i3 = 3 < cnt ? 3 : cnt - 1;
        cur[0] = __ldg((const float4*)(xb + (size_t)s_list[i0] * ROW) + tid);
        cur[1] = __ldg((const float4*)(xb + (size_t)s_list[i1] * ROW) + tid);
        cur[2] = __ldg((const float4*)(xb + (size_t)s_list[i2] * ROW) + tid);
        cur[3] = __ldg((const float4*)(xb + (size_t)s_list[i3] * ROW) + tid);
    }

    for (int g = 0; g < G; ++g) {
        // prefetch next group
        float4 nxt[4];
        if (g + 1 < G) {
            const int base_i = (g + 1) * 4;
            int idx[4];
            #pragma unroll
            for (int j = 0; j < 4; ++j) {
                int i = base_i + j;
                idx[j] = s_list[i < cnt ? i : cnt - 1];
            }
            #pragma unroll
            for (int j = 0; j < 4; ++j)
                nxt[j] = __ldg((const float4*)(xb + (size_t)idx[j] * ROW) + tid);
        }

        // partial dots for current 4 rows
        float p[4];
        #pragma unroll
        for (int j = 0; j < 4; ++j)
            p[j] = cur[j].x * wv.x + cur[j].y * wv.y + cur[j].z * wv.z + cur[j].w * wv.w;

        #pragma unroll
        for (int off = 16; off; off >>= 1) {
            #pragma unroll
            for (int j = 0; j < 4; ++j)
                p[j] += __shfl_xor_sync(0xFFFFFFFFu, p[j], off);
        }
        const int buf = g & 1;
        if (lane == 0) {
            #pragma unroll
            for (int j = 0; j < 4; ++j) s_red[buf][wid][j] = p[j];
        }
        __syncthreads();

        // full scores (identical value in every thread -> d stays block-uniform)
        float s[4];
        #pragma unroll
        for (int j = 0; j < 4; ++j) {
            const float tot = s_red[buf][0][j] + s_red[buf][1][j]
                            + s_red[buf][2][j] + s_red[buf][3][j];
            s[j] = (g * 4 + j < cnt) ? (tot * 0.125f + bv) : -FLT_MAX;
        }

        // online softmax update (list order -> deterministic)
        const float gm   = fmaxf(fmaxf(s[0], s[1]), fmaxf(s[2], s[3]));
        const float mnew = fmaxf(m, gm);
        const float sc   = __expf(m - mnew);   // exactly 0 on first group
        d *= sc;
        acc.x *= sc; acc.y *= sc; acc.z *= sc; acc.w *= sc;
        #pragma unroll
        for (int j = 0; j < 4; ++j) {
            const float e = __expf(s[j] - mnew);
            d += e;
            acc.x = fmaf(e, cur[j].x, acc.x);
            acc.y = fmaf(e, cur[j].y, acc.y);
            acc.z = fmaf(e, cur[j].z, acc.z);
            acc.w = fmaf(e, cur[j].w, acc.w);
        }
        m = mnew;

        #pragma unroll
        for (int j = 0; j < 4; ++j) cur[j] = nxt[j];
    }

    const float inv = 1.f / d;
    acc.x *= inv; acc.y *= inv; acc.z *= inv; acc.w *= inv;
    ((float4*)out)[out_idx] = acc;
}

extern "C" void kernel_launch(void* const* d_in, const int* in_sizes, int n_in,
                              void* d_out, int out_size) {
    const float* x    = (const float*)d_in[0];
    const float* W    = (const float*)d_in[1];
    const float* bias = (const float*)d_in[2];
    const int*   seg  = (const int*)d_in[3];

    build_lists_kernel<<<CC, 128>>>(seg);
    pool_kernel<<<dim3(CC, BB), 128>>>(x, W, bias, (float*)d_out);
}

// round 5
// speedup vs baseline: 1.1114x; 1.0994x over previous
#include <cuda_runtime.h>
#include <float.h>

// GraphPooling: B=16, N=4096, F=8, H=64, C=256
// out[b,c,:,:] = sum_{n: seg[n]==c} softmax_w(b,n) * x[b,n,:,:]
// score[b,n] = (sum_e x[b,n,e] * W[h(e)]) / F + bias ; softmax per (b, segment).
// Single-pass online softmax; each warp owns whole rows -> no in-loop barriers.

#define BB   16
#define NN   4096
#define FF   8
#define HH   64
#define CC   256
#define ROW  512
#define MAXPER 96

__device__ int g_list[CC * MAXPER];
__device__ int g_cnt[CC];

// Block c compacts segment c. Thread t owns chunk [t*32, t*32+32):
// concatenated order = increasing node index (deterministic).
__global__ __launch_bounds__(128) void build_lists_kernel(const int* __restrict__ seg) {
    __shared__ int s_seg[NN];
    __shared__ int s_cnt[128];
    __shared__ int s_wtot[4];

    const int c    = blockIdx.x;
    const int tid  = threadIdx.x;
    const int lane = tid & 31;
    const int wid  = tid >> 5;

    for (int i = tid; i < NN / 4; i += 128)
        ((int4*)s_seg)[i] = ((const int4*)seg)[i];
    __syncthreads();

    const int base = tid * 32;
    int cnt = 0;
    #pragma unroll
    for (int j = 0; j < 32; ++j) cnt += (s_seg[base + j] == c);

    int incl = cnt;
    #pragma unroll
    for (int off = 1; off < 32; off <<= 1) {
        const int v = __shfl_up_sync(0xFFFFFFFFu, incl, off);
        if (lane >= off) incl += v;
    }
    if (lane == 31) s_wtot[wid] = incl;
    s_cnt[tid] = incl - cnt;
    __syncthreads();
    int wbase = 0;
    #pragma unroll
    for (int w = 0; w < 4; ++w) { if (w < wid) wbase += s_wtot[w]; }
    const int offset = s_cnt[tid] + wbase;

    if (tid == 127) {
        const int total = offset + cnt;
        g_cnt[c] = total < MAXPER ? total : MAXPER;
    }

    int p = offset;
    #pragma unroll
    for (int j = 0; j < 32; ++j) {
        if (s_seg[base + j] == c) {
            if (p < MAXPER) g_list[c * MAXPER + p] = base + j;
            ++p;
        }
    }
}

// One block per (c, b), 128 threads = 4 warps. Warp w handles rows w, w+4, ...
// Lane owns row float4 positions {lane, lane+32, lane+64, lane+96}.
__global__ __launch_bounds__(128) void pool_kernel(
    const float* __restrict__ x,
    const float* __restrict__ W,
    const float* __restrict__ bias,
    float* __restrict__ out)
{
    __shared__ int    s_list[MAXPER];
    __shared__ float  s_m[4], s_d[4];
    __shared__ float4 s_acc[4][128];   // 8 KB

    const int c    = blockIdx.x;
    const int b    = blockIdx.y;
    const int tid  = threadIdx.x;
    const int wid  = tid >> 5;
    const int lane = tid & 31;

    const int cnt = g_cnt[c];
    const size_t out_idx = (size_t)(b * CC + c) * (ROW / 4) + tid;
    if (cnt == 0) {
        ((float4*)out)[out_idx] = make_float4(0.f, 0.f, 0.f, 0.f);
        return;
    }
    if (tid < cnt) s_list[tid] = g_list[c * MAXPER + tid];
    __syncthreads();

    // W tile: h((4p)&63) identical for p, p+32, p+64, p+96
    const float4 wv = *(const float4*)(W + ((lane * 4) & 63));
    const float  bv = __ldg(bias);
    const float* xb = x + (size_t)b * NN * ROW;

    float  m = -FLT_MAX, d = 0.f;
    float4 a0 = make_float4(0.f, 0.f, 0.f, 0.f), a1 = a0, a2 = a0, a3 = a0;

    if (wid < cnt) {
        const float4* r = (const float4*)(xb + (size_t)s_list[wid] * ROW);
        float4 c0 = __ldg(r + lane),      c1 = __ldg(r + lane + 32),
               c2 = __ldg(r + lane + 64), c3 = __ldg(r + lane + 96);

        for (int i = wid; i < cnt; i += 4) {
            // prefetch next row for this warp
            float4 n0 = c0, n1 = c1, n2 = c2, n3 = c3;
            if (i + 4 < cnt) {
                const float4* rn = (const float4*)(xb + (size_t)s_list[i + 4] * ROW);
                n0 = __ldg(rn + lane);      n1 = __ldg(rn + lane + 32);
                n2 = __ldg(rn + lane + 64); n3 = __ldg(rn + lane + 96);
            }

            // score: warp-only reduce
            float p = c0.x * wv.x + c0.y * wv.y + c0.z * wv.z + c0.w * wv.w;
            p      += c1.x * wv.x + c1.y * wv.y + c1.z * wv.z + c1.w * wv.w;
            p      += c2.x * wv.x + c2.y * wv.y + c2.z * wv.z + c2.w * wv.w;
            p      += c3.x * wv.x + c3.y * wv.y + c3.z * wv.z + c3.w * wv.w;
            #pragma unroll
            for (int off = 16; off; off >>= 1)
                p += __shfl_xor_sync(0xFFFFFFFFu, p, off);
            const float s = p * 0.125f + bv;

            // online update (per-warp, list order)
            const float mnew = fmaxf(m, s);
            const float sc   = __expf(m - mnew);   // exactly 0 on first row
            const float e    = __expf(s - mnew);
            d = d * sc + e;
            a0.x = a0.x * sc + e * c0.x; a0.y = a0.y * sc + e * c0.y;
            a0.z = a0.z * sc + e * c0.z; a0.w = a0.w * sc + e * c0.w;
            a1.x = a1.x * sc + e * c1.x; a1.y = a1.y * sc + e * c1.y;
            a1.z = a1.z * sc + e * c1.z; a1.w = a1.w * sc + e * c1.w;
            a2.x = a2.x * sc + e * c2.x; a2.y = a2.y * sc + e * c2.y;
            a2.z = a2.z * sc + e * c2.z; a2.w = a2.w * sc + e * c2.w;
            a3.x = a3.x * sc + e * c3.x; a3.y = a3.y * sc + e * c3.y;
            a3.z = a3.z * sc + e * c3.z; a3.w = a3.w * sc + e * c3.w;
            m = mnew;

            c0 = n0; c1 = n1; c2 = n2; c3 = n3;
        }
    }

    // merge 4 warp partials (fixed order -> deterministic)
    if (lane == 0) { s_m[wid] = m; s_d[wid] = d; }
    s_acc[wid][lane]      = a0;
    s_acc[wid][lane + 32] = a1;
    s_acc[wid][lane + 64] = a2;
    s_acc[wid][lane + 96] = a3;
    __syncthreads();

    const float M  = fmaxf(fmaxf(s_m[0], s_m[1]), fmaxf(s_m[2], s_m[3]));
    const float f0 = __expf(s_m[0] - M), f1 = __expf(s_m[1] - M),
                f2 = __expf(s_m[2] - M), f3 = __expf(s_m[3] - M);
    const float D  = f0 * s_d[0] + f1 * s_d[1] + f2 * s_d[2] + f3 * s_d[3];
    const float inv = 1.f / D;

    const float4 r0 = s_acc[0][tid], r1 = s_acc[1][tid],
                 r2 = s_acc[2][tid], r3 = s_acc[3][tid];
    float4 o;
    o.x = (f0 * r0.x + f1 * r1.x + f2 * r2.x + f3 * r3.x) * inv;
    o.y = (f0 * r0.y + f1 * r1.y + f2 * r2.y + f3 * r3.y) * inv;
    o.z = (f0 * r0.z + f1 * r1.z + f2 * r2.z + f3 * r3.z) * inv;
    o.w = (f0 * r0.w + f1 * r1.w + f2 * r2.w + f3 * r3.w) * inv;
    ((float4*)out)[out_idx] = o;
}

extern "C" void kernel_launch(void* const* d_in, const int* in_sizes, int n_in,
                              void* d_out, int out_size) {
    const float* x    = (const float*)d_in[0];
    const float* W    = (const float*)d_in[1];
    const float* bias = (const float*)d_in[2];
    const int*   seg  = (const int*)d_in[3];

    build_lists_kernel<<<CC, 128>>>(seg);
    pool_kernel<<<dim3(CC, BB), 128>>>(x, W, bias, (float*)d_out);
}